// round 10
// baseline (speedup 1.0000x reference)
#include <cuda_runtime.h>
#include <cuda_fp16.h>
#include <cstdint>

#define S_LEN 4096
#define D_MODEL 512
#define KV_W 1024
#define N_HEADS 8

// ---------------- scratch (fp16 intermediates) ----------------
__device__ __half g_q[S_LEN * D_MODEL];    // pre-scaled by 0.125*log2(e)
__device__ __half g_kv[S_LEN * KV_W];
__device__ __half g_att[S_LEN * D_MODEL];

// ---------------- helpers ----------------
__device__ __forceinline__ uint32_t smem_u32(const void* p) {
    return (uint32_t)__cvta_generic_to_shared(p);
}
__device__ __forceinline__ uint32_t pk2(float lo, float hi) {
    __half2 h = __floats2half2_rn(lo, hi);
    return *reinterpret_cast<uint32_t*>(&h);
}
__device__ __forceinline__ float fexp2(float x) {
    float y; asm("ex2.approx.f32 %0, %1;" : "=f"(y) : "f"(x)); return y;
}
__device__ __forceinline__ void ldm_x4(uint32_t& r0, uint32_t& r1, uint32_t& r2, uint32_t& r3, uint32_t a) {
    asm volatile("ldmatrix.sync.aligned.m8n8.x4.shared.b16 {%0,%1,%2,%3}, [%4];"
                 : "=r"(r0), "=r"(r1), "=r"(r2), "=r"(r3) : "r"(a));
}
__device__ __forceinline__ void ldm_x4_t(uint32_t& r0, uint32_t& r1, uint32_t& r2, uint32_t& r3, uint32_t a) {
    asm volatile("ldmatrix.sync.aligned.m8n8.x4.trans.shared.b16 {%0,%1,%2,%3}, [%4];"
                 : "=r"(r0), "=r"(r1), "=r"(r2), "=r"(r3) : "r"(a));
}
// D += A(16x16) * B(16x8), f16 in, f32 accum
__device__ __forceinline__ void mma_f16(float* d, const uint32_t* a, uint32_t b0, uint32_t b1) {
    asm volatile(
        "mma.sync.aligned.m16n8k16.row.col.f32.f16.f16.f32 "
        "{%0,%1,%2,%3}, {%4,%5,%6,%7}, {%8,%9}, {%0,%1,%2,%3};"
        : "+f"(d[0]), "+f"(d[1]), "+f"(d[2]), "+f"(d[3])
        : "r"(a[0]), "r"(a[1]), "r"(a[2]), "r"(a[3]), "r"(b0), "r"(b1));
}
__device__ __forceinline__ void cp_async16(uint32_t dst, const void* src) {
    asm volatile("cp.async.cg.shared.global [%0], [%1], 16;" :: "r"(dst), "l"(src));
}
__device__ __forceinline__ void cp_commit() { asm volatile("cp.async.commit_group;" ::: "memory"); }
template<int N> __device__ __forceinline__ void cp_wait() {
    asm volatile("cp.async.wait_group %0;" :: "n"(N) : "memory");
}

// ---------------- fp16 tensor-core GEMM ----------------
// C[M,N] = A[M,512] @ B[512,N] + bias, BM=128 BN=128 BK=32, 256 thr (8 warps 4m x 2n).
#define AP_H 40     // As pitch, halves (80B rows: 20r mod 32 distinct bank groups)
#define BP_H 136    // Bs pitch, halves (272B rows: 4r mod 32)
#define AS_SZ (128 * AP_H)   // 5120 halves
#define BS_SZ (32 * BP_H)    // 4352 halves

template<bool A_HALF, bool OUT_HALF>
__device__ __forceinline__ void gemm_tc(
    const void* Av, const float* __restrict__ B, const float* __restrict__ bias,
    void* Cv, int N, int row0, int col0, float scale, __half* smh)
{
    __half* As = smh;                    // [2][128][40]
    __half* Bs = smh + 2 * AS_SZ;        // [2][32][136]

    const int tid = threadIdx.x;
    const int lane = tid & 31, warp = tid >> 5;
    const int wm = (warp & 3) * 32, wn = (warp >> 2) * 64;
    const int g = lane >> 2, t = lane & 3;

    const float* Af = (const float*)Av;
    const __half* Ah = (const __half*)Av;

    const int arow = tid >> 1, acolb = (tid & 1) * 16;
    const int brow = tid >> 3, bcolb = (tid & 7) * 16;

    float4 pa[4]; uint4 pah[2]; float4 pb[4];

    auto load_tiles = [&](int k0) {
        if (A_HALF) {
            const __half* p = Ah + (size_t)(row0 + arow) * 512 + k0 + acolb;
            pah[0] = *(const uint4*)(p);
            pah[1] = *(const uint4*)(p + 8);
        } else {
            const float* p = Af + (size_t)(row0 + arow) * 512 + k0 + acolb;
#pragma unroll
            for (int j = 0; j < 4; j++) pa[j] = *(const float4*)(p + j * 4);
        }
        const float* q = B + (size_t)(k0 + brow) * N + col0 + bcolb;
#pragma unroll
        for (int j = 0; j < 4; j++) pb[j] = *(const float4*)(q + j * 4);
    };
    auto store_tiles = [&](int buf) {
        __half* as = As + buf * AS_SZ;
        __half* bs = Bs + buf * BS_SZ;
        if (A_HALF) {
            *(uint4*)(as + arow * AP_H + acolb) = pah[0];
            *(uint4*)(as + arow * AP_H + acolb + 8) = pah[1];
        } else {
            uint4 u0, u1;
            u0.x = pk2(pa[0].x, pa[0].y); u0.y = pk2(pa[0].z, pa[0].w);
            u0.z = pk2(pa[1].x, pa[1].y); u0.w = pk2(pa[1].z, pa[1].w);
            u1.x = pk2(pa[2].x, pa[2].y); u1.y = pk2(pa[2].z, pa[2].w);
            u1.z = pk2(pa[3].x, pa[3].y); u1.w = pk2(pa[3].z, pa[3].w);
            *(uint4*)(as + arow * AP_H + acolb) = u0;
            *(uint4*)(as + arow * AP_H + acolb + 8) = u1;
        }
        uint4 v0, v1;
        v0.x = pk2(pb[0].x, pb[0].y); v0.y = pk2(pb[0].z, pb[0].w);
        v0.z = pk2(pb[1].x, pb[1].y); v0.w = pk2(pb[1].z, pb[1].w);
        v1.x = pk2(pb[2].x, pb[2].y); v1.y = pk2(pb[2].z, pb[2].w);
        v1.z = pk2(pb[3].x, pb[3].y); v1.w = pk2(pb[3].z, pb[3].w);
        *(uint4*)(bs + brow * BP_H + bcolb) = v0;
        *(uint4*)(bs + brow * BP_H + bcolb + 8) = v1;
    };

    float acc[2][8][4];
#pragma unroll
    for (int mt = 0; mt < 2; mt++)
#pragma unroll
        for (int nt = 0; nt < 8; nt++)
#pragma unroll
            for (int c = 0; c < 4; c++) acc[mt][nt][c] = 0.f;

    load_tiles(0);
    store_tiles(0);
    __syncthreads();

    const uint32_t asU = smem_u32(As);
    const uint32_t bsU = smem_u32(Bs);

    for (int it = 0; it < 16; it++) {
        const int cur = it & 1;
        if (it < 15) load_tiles((it + 1) * 32);

        const uint32_t aB = asU + cur * (AS_SZ * 2);
        const uint32_t bB = bsU + cur * (BS_SZ * 2);
#pragma unroll
        for (int ks = 0; ks < 2; ks++) {
            uint32_t a[2][4];
#pragma unroll
            for (int mt = 0; mt < 2; mt++) {
                uint32_t ad = aB + ((wm + mt * 16 + (lane & 15)) * AP_H + ks * 16 + (lane >> 4) * 8) * 2;
                ldm_x4(a[mt][0], a[mt][1], a[mt][2], a[mt][3], ad);
            }
#pragma unroll
            for (int ntp = 0; ntp < 4; ntp++) {
                uint32_t r0, r1, r2, r3;
                uint32_t bd = bB + ((ks * 16 + (lane & 7) + ((lane >> 3) & 1) * 8) * BP_H
                                    + wn + ntp * 16 + ((lane >> 4) << 3)) * 2;
                ldm_x4_t(r0, r1, r2, r3, bd);
                mma_f16(acc[0][2 * ntp], a[0], r0, r1);
                mma_f16(acc[0][2 * ntp + 1], a[0], r2, r3);
                mma_f16(acc[1][2 * ntp], a[1], r0, r1);
                mma_f16(acc[1][2 * ntp + 1], a[1], r2, r3);
            }
        }

        if (it < 15) { store_tiles(cur ^ 1); __syncthreads(); }
    }

    // epilogue
#pragma unroll
    for (int mt = 0; mt < 2; mt++) {
        const int r = row0 + wm + mt * 16 + g;
#pragma unroll
        for (int nt = 0; nt < 8; nt++) {
            const int c = col0 + wn + nt * 8 + 2 * t;
            const float2 bv = *(const float2*)(bias + c);
            if (OUT_HALF) {
                __half* C = (__half*)Cv;
                *(__half2*)(C + (size_t)r * N + c) =
                    __floats2half2_rn((acc[mt][nt][0] + bv.x) * scale, (acc[mt][nt][1] + bv.y) * scale);
                *(__half2*)(C + (size_t)(r + 8) * N + c) =
                    __floats2half2_rn((acc[mt][nt][2] + bv.x) * scale, (acc[mt][nt][3] + bv.y) * scale);
            } else {
                float* C = (float*)Cv;
                *(float2*)(C + (size_t)r * N + c) =
                    make_float2(acc[mt][nt][0] + bv.x, acc[mt][nt][1] + bv.y);
                *(float2*)(C + (size_t)(r + 8) * N + c) =
                    make_float2(acc[mt][nt][2] + bv.x, acc[mt][nt][3] + bv.y);
            }
        }
    }
}

#define G_SMEM_HALVES (2 * AS_SZ + 2 * BS_SZ)   // 18944 halves = 37888 B

__global__ __launch_bounds__(256) void proj_dual(
    const float* __restrict__ query, const float* __restrict__ value,
    const float* __restrict__ wq, const float* __restrict__ wqb,
    const float* __restrict__ wkv, const float* __restrict__ wkvb,
    __half* __restrict__ outq, __half* __restrict__ outkv)
{
    __shared__ __half smh[G_SMEM_HALVES];
    const int bx = blockIdx.x, by = blockIdx.y;
    const float QSCALE = 0.125f * 1.44269504089f;   // fold softmax scale + log2(e)
    if (bx < 4)
        gemm_tc<false, true>(query, wq, wqb, outq, D_MODEL, by * 128, bx * 128, QSCALE, smh);
    else
        gemm_tc<false, true>(value, wkv, wkvb, outkv, KV_W, by * 128, (bx - 4) * 128, 1.0f, smh);
}

__global__ __launch_bounds__(256) void out_proj(
    const __half* __restrict__ A, const float* __restrict__ B,
    const float* __restrict__ bias, float* __restrict__ C)
{
    __shared__ __half smh[G_SMEM_HALVES];
    gemm_tc<true, false>(A, B, bias, C, D_MODEL, blockIdx.y * 128, blockIdx.x * 128, 1.0f, smh);
}

// ---------------- causal flash attention, fp16 mma + cp.async ----------------
// 128 threads = 4 warps; CTA tile 128q x 64k; warp tile 32q x 64k.
// Softmax in exp2 domain (Q pre-scaled by 0.125*log2e at projection).
#define QP 72            // pitches in halves (144B rows)
#define QS_SZ (128 * QP)
#define KT_SZ (64 * QP)
#define FA_SMEM_BYTES ((QS_SZ + 4 * KT_SZ) * 2)   // 55296

__global__ __launch_bounds__(128) void flash_attn_h(
    const __half* __restrict__ Qh, const __half* __restrict__ KVh,
    __half* __restrict__ Oh)
{
    extern __shared__ __half smh[];
    __half* Qs = smh;
    __half* KsB = smh + QS_SZ;             // [2][64][72]
    __half* VsB = smh + QS_SZ + 2 * KT_SZ; // [2][64][72]

    const int qb = gridDim.x - 1 - blockIdx.x;   // heavy first
    const int h  = blockIdx.y;
    const int tid = threadIdx.x;
    const int lane = tid & 31, warp = tid >> 5;
    const int g = lane >> 2, t = lane & 3;
    const int wq = warp * 32;
    const int q0 = qb * 128;
    const int ntiles = 2 * qb + 2;

    const uint32_t qsU = smem_u32(Qs);
    const uint32_t ksU = smem_u32(KsB);
    const uint32_t vsU = smem_u32(VsB);

    // stage Q (1024 16B chunks)
#pragma unroll
    for (int i = 0; i < 8; i++) {
        const int c = tid + 128 * i;
        const int row = c >> 3, seg = (c & 7) * 8;
        cp_async16(qsU + (row * QP + seg) * 2,
                   Qh + (size_t)(q0 + row) * D_MODEL + h * 64 + seg);
    }
    auto stage_kv = [&](int kb, int buf) {
        const int k0 = kb * 64;
        const uint32_t kd = ksU + buf * KT_SZ * 2;
        const uint32_t vd = vsU + buf * KT_SZ * 2;
#pragma unroll
        for (int i = 0; i < 4; i++) {
            const int c = tid + 128 * i;
            const int row = c >> 3, seg = (c & 7) * 8;
            const size_t base = (size_t)(k0 + row) * KV_W + h * 64 + seg;
            cp_async16(kd + (row * QP + seg) * 2, KVh + base);
            cp_async16(vd + (row * QP + seg) * 2, KVh + base + D_MODEL);
        }
    };
    stage_kv(0, 0);
    cp_commit();

    float o[2][8][4];
    float m_i[4], l_i[4];
#pragma unroll
    for (int i = 0; i < 4; i++) { m_i[i] = -1e30f; l_i[i] = 0.f; }
#pragma unroll
    for (int mt = 0; mt < 2; mt++)
#pragma unroll
        for (int nt = 0; nt < 8; nt++)
#pragma unroll
            for (int c = 0; c < 4; c++) o[mt][nt][c] = 0.f;

    for (int kb = 0; kb < ntiles; kb++) {
        const int buf = kb & 1;
        const int k0 = kb * 64;

        __syncthreads();   // prior compute done before prefetch overwrites buf^1
        if (kb + 1 < ntiles) { stage_kv(kb + 1, buf ^ 1); cp_commit(); cp_wait<1>(); }
        else cp_wait<0>();
        __syncthreads();

        const uint32_t kB = ksU + buf * KT_SZ * 2;
        const uint32_t vB = vsU + buf * KT_SZ * 2;

        // ---- S = Q K^T ----
        float s[2][8][4];
#pragma unroll
        for (int mt = 0; mt < 2; mt++)
#pragma unroll
            for (int nt = 0; nt < 8; nt++)
#pragma unroll
                for (int c = 0; c < 4; c++) s[mt][nt][c] = 0.f;

#pragma unroll
        for (int ks = 0; ks < 4; ks++) {
            uint32_t a[2][4];
#pragma unroll
            for (int mt = 0; mt < 2; mt++) {
                uint32_t ad = qsU + ((wq + mt * 16 + (lane & 15)) * QP + ks * 16 + (lane >> 4) * 8) * 2;
                ldm_x4(a[mt][0], a[mt][1], a[mt][2], a[mt][3], ad);
            }
#pragma unroll
            for (int ntp = 0; ntp < 4; ntp++) {
                uint32_t r0, r1, r2, r3;
                uint32_t bd = kB + ((ntp * 16 + (lane & 7) + ((lane >> 4) << 3)) * QP
                                    + ks * 16 + ((lane >> 3) & 1) * 8) * 2;
                ldm_x4(r0, r1, r2, r3, bd);   // non-trans: Ks is [key][hd] = [n][k]
                mma_f16(s[0][2 * ntp], a[0], r0, r1);
                mma_f16(s[0][2 * ntp + 1], a[0], r2, r3);
                mma_f16(s[1][2 * ntp], a[1], r0, r1);
                mma_f16(s[1][2 * ntp + 1], a[1], r2, r3);
            }
        }

        // causal mask (diagonal-region tiles only)
        if (kb >= 2 * qb) {
#pragma unroll
            for (int mt = 0; mt < 2; mt++)
#pragma unroll
                for (int nt = 0; nt < 8; nt++)
#pragma unroll
                    for (int c = 0; c < 4; c++) {
                        const int row = q0 + wq + mt * 16 + g + (c >> 1) * 8;
                        const int col = k0 + nt * 8 + 2 * t + (c & 1);
                        if (col > row) s[mt][nt][c] = -1e30f;
                    }
        }

        // ---- online softmax (exp2 domain) ----
#pragma unroll
        for (int mt = 0; mt < 2; mt++) {
#pragma unroll
            for (int sr = 0; sr < 2; sr++) {
                const int idx = mt * 2 + sr;
                float mx = -1e30f;
#pragma unroll
                for (int nt = 0; nt < 8; nt++)
                    mx = fmaxf(mx, fmaxf(s[mt][nt][2 * sr], s[mt][nt][2 * sr + 1]));
                mx = fmaxf(mx, __shfl_xor_sync(0xffffffffu, mx, 1, 4));
                mx = fmaxf(mx, __shfl_xor_sync(0xffffffffu, mx, 2, 4));

                const float m_new = fmaxf(m_i[idx], mx);
                const float alpha = fexp2(m_i[idx] - m_new);
                float rs = 0.f;
#pragma unroll
                for (int nt = 0; nt < 8; nt++) {
                    const float p0 = fexp2(s[mt][nt][2 * sr] - m_new);
                    const float p1 = fexp2(s[mt][nt][2 * sr + 1] - m_new);
                    s[mt][nt][2 * sr] = p0;
                    s[mt][nt][2 * sr + 1] = p1;
                    rs += p0 + p1;
                }
                rs += __shfl_xor_sync(0xffffffffu, rs, 1, 4);
                rs += __shfl_xor_sync(0xffffffffu, rs, 2, 4);

                l_i[idx] = l_i[idx] * alpha + rs;
                m_i[idx] = m_new;
#pragma unroll
                for (int nt = 0; nt < 8; nt++) {
                    o[mt][nt][2 * sr] *= alpha;
                    o[mt][nt][2 * sr + 1] *= alpha;
                }
            }
        }

        // ---- O += P V (P straight from registers) ----
#pragma unroll
        for (int ksp = 0; ksp < 4; ksp++) {
            uint32_t aP[2][4];
#pragma unroll
            for (int mt = 0; mt < 2; mt++) {
                aP[mt][0] = pk2(s[mt][2 * ksp][0], s[mt][2 * ksp][1]);
                aP[mt][1] = pk2(s[mt][2 * ksp][2], s[mt][2 * ksp][3]);
                aP[mt][2] = pk2(s[mt][2 * ksp + 1][0], s[mt][2 * ksp + 1][1]);
                aP[mt][3] = pk2(s[mt][2 * ksp + 1][2], s[mt][2 * ksp + 1][3]);
            }
#pragma unroll
            for (int ntp = 0; ntp < 4; ntp++) {
                uint32_t r0, r1, r2, r3;
                uint32_t bd = vB + ((ksp * 16 + (lane & 7) + ((lane >> 3) & 1) * 8) * QP
                                    + ntp * 16 + ((lane >> 4) << 3)) * 2;
                ldm_x4_t(r0, r1, r2, r3, bd);   // trans: Vs is [key][hd] = [k][n]
                mma_f16(o[0][2 * ntp], aP[0], r0, r1);
                mma_f16(o[0][2 * ntp + 1], aP[0], r2, r3);
                mma_f16(o[1][2 * ntp], aP[1], r0, r1);
                mma_f16(o[1][2 * ntp + 1], aP[1], r2, r3);
            }
        }
    }

    // normalize + store (half)
#pragma unroll
    for (int mt = 0; mt < 2; mt++) {
#pragma unroll
        for (int sr = 0; sr < 2; sr++) {
            const float inv = 1.f / l_i[mt * 2 + sr];
            const int r = q0 + wq + mt * 16 + g + 8 * sr;
#pragma unroll
            for (int nt = 0; nt < 8; nt++) {
                *(__half2*)(Oh + (size_t)r * D_MODEL + h * 64 + nt * 8 + 2 * t) =
                    __floats2half2_rn(o[mt][nt][2 * sr] * inv, o[mt][nt][2 * sr + 1] * inv);
            }
        }
    }
}

// ---------------- launch ----------------
extern "C" void kernel_launch(void* const* d_in, const int* in_sizes, int n_in,
                              void* d_out, int out_size)
{
    const float* query = (const float*)d_in[0];
    const float* value = (const float*)d_in[1];
    // d_in[2]: additive causal mask -> handled structurally
    const float* wq_k  = (const float*)d_in[3];
    const float* wq_b  = (const float*)d_in[4];
    const float* wkv_k = (const float*)d_in[5];
    const float* wkv_b = (const float*)d_in[6];
    const float* wo_k  = (const float*)d_in[7];
    const float* wo_b  = (const float*)d_in[8];
    float* out = (float*)d_out;

    __half *q_ptr = nullptr, *kv_ptr = nullptr, *att_ptr = nullptr;
    cudaGetSymbolAddress((void**)&q_ptr,  g_q);
    cudaGetSymbolAddress((void**)&kv_ptr, g_kv);
    cudaGetSymbolAddress((void**)&att_ptr, g_att);

    proj_dual<<<dim3(12, 32), 256>>>(query, value, wq_k, wq_b, wkv_k, wkv_b,
                                     q_ptr, kv_ptr);

    cudaFuncSetAttribute(flash_attn_h, cudaFuncAttributeMaxDynamicSharedMemorySize, FA_SMEM_BYTES);
    flash_attn_h<<<dim3(S_LEN / 128, N_HEADS), 128, FA_SMEM_BYTES>>>(q_ptr, kv_ptr, att_ptr);

    out_proj<<<dim3(4, 32), 256>>>(att_ptr, wo_k, wo_b, out);
}

// round 11
// speedup vs baseline: 1.0036x; 1.0036x over previous
#include <cuda_runtime.h>
#include <cuda_fp16.h>
#include <cstdint>

#define S_LEN 4096
#define D_MODEL 512
#define KV_W 1024
#define N_HEADS 8

// ---------------- scratch (fp16 intermediates) ----------------
__device__ __half g_q[S_LEN * D_MODEL];    // pre-scaled by 0.125*log2(e)
__device__ __half g_kv[S_LEN * KV_W];
__device__ __half g_att[S_LEN * D_MODEL];

// ---------------- helpers ----------------
__device__ __forceinline__ uint32_t smem_u32(const void* p) {
    return (uint32_t)__cvta_generic_to_shared(p);
}
__device__ __forceinline__ uint32_t pk2(float lo, float hi) {
    __half2 h = __floats2half2_rn(lo, hi);
    return *reinterpret_cast<uint32_t*>(&h);
}
__device__ __forceinline__ float fexp2(float x) {
    float y; asm("ex2.approx.f32 %0, %1;" : "=f"(y) : "f"(x)); return y;
}
__device__ __forceinline__ void ldm_x4(uint32_t& r0, uint32_t& r1, uint32_t& r2, uint32_t& r3, uint32_t a) {
    asm volatile("ldmatrix.sync.aligned.m8n8.x4.shared.b16 {%0,%1,%2,%3}, [%4];"
                 : "=r"(r0), "=r"(r1), "=r"(r2), "=r"(r3) : "r"(a));
}
__device__ __forceinline__ void ldm_x4_t(uint32_t& r0, uint32_t& r1, uint32_t& r2, uint32_t& r3, uint32_t a) {
    asm volatile("ldmatrix.sync.aligned.m8n8.x4.trans.shared.b16 {%0,%1,%2,%3}, [%4];"
                 : "=r"(r0), "=r"(r1), "=r"(r2), "=r"(r3) : "r"(a));
}
// D += A(16x16) * B(16x8), f16 in, f32 accum
__device__ __forceinline__ void mma_f16(float* d, const uint32_t* a, uint32_t b0, uint32_t b1) {
    asm volatile(
        "mma.sync.aligned.m16n8k16.row.col.f32.f16.f16.f32 "
        "{%0,%1,%2,%3}, {%4,%5,%6,%7}, {%8,%9}, {%0,%1,%2,%3};"
        : "+f"(d[0]), "+f"(d[1]), "+f"(d[2]), "+f"(d[3])
        : "r"(a[0]), "r"(a[1]), "r"(a[2]), "r"(a[3]), "r"(b0), "r"(b1));
}
__device__ __forceinline__ void cp_async16(uint32_t dst, const void* src) {
    asm volatile("cp.async.cg.shared.global [%0], [%1], 16;" :: "r"(dst), "l"(src));
}
__device__ __forceinline__ void cp_commit() { asm volatile("cp.async.commit_group;" ::: "memory"); }
template<int N> __device__ __forceinline__ void cp_wait() {
    asm volatile("cp.async.wait_group %0;" :: "n"(N) : "memory");
}

// ---------------- fp16 tensor-core GEMM ----------------
// C[M,N] = A[M,512] @ B[512,N] + bias, BM=128 BN=128 BK=32, 256 thr (8 warps 4m x 2n).
#define AP_H 40     // As pitch, halves (80B rows: 20r mod 32 distinct bank groups)
#define BP_H 136    // Bs pitch, halves (272B rows: 4r mod 32)
#define AS_SZ (128 * AP_H)   // 5120 halves
#define BS_SZ (32 * BP_H)    // 4352 halves

template<bool A_HALF, bool OUT_HALF>
__device__ __forceinline__ void gemm_tc(
    const void* Av, const float* __restrict__ B, const float* __restrict__ bias,
    void* Cv, int N, int row0, int col0, float scale, __half* smh)
{
    __half* As = smh;                    // [2][128][40]
    __half* Bs = smh + 2 * AS_SZ;        // [2][32][136]

    const int tid = threadIdx.x;
    const int lane = tid & 31, warp = tid >> 5;
    const int wm = (warp & 3) * 32, wn = (warp >> 2) * 64;
    const int g = lane >> 2, t = lane & 3;

    const float* Af = (const float*)Av;
    const __half* Ah = (const __half*)Av;

    const int arow = tid >> 1, acolb = (tid & 1) * 16;
    const int brow = tid >> 3, bcolb = (tid & 7) * 16;

    float4 pa[4]; uint4 pah[2]; float4 pb[4];

    auto load_tiles = [&](int k0) {
        if (A_HALF) {
            const __half* p = Ah + (size_t)(row0 + arow) * 512 + k0 + acolb;
            pah[0] = *(const uint4*)(p);
            pah[1] = *(const uint4*)(p + 8);
        } else {
            const float* p = Af + (size_t)(row0 + arow) * 512 + k0 + acolb;
#pragma unroll
            for (int j = 0; j < 4; j++) pa[j] = *(const float4*)(p + j * 4);
        }
        const float* q = B + (size_t)(k0 + brow) * N + col0 + bcolb;
#pragma unroll
        for (int j = 0; j < 4; j++) pb[j] = *(const float4*)(q + j * 4);
    };
    auto store_tiles = [&](int buf) {
        __half* as = As + buf * AS_SZ;
        __half* bs = Bs + buf * BS_SZ;
        if (A_HALF) {
            *(uint4*)(as + arow * AP_H + acolb) = pah[0];
            *(uint4*)(as + arow * AP_H + acolb + 8) = pah[1];
        } else {
            uint4 u0, u1;
            u0.x = pk2(pa[0].x, pa[0].y); u0.y = pk2(pa[0].z, pa[0].w);
            u0.z = pk2(pa[1].x, pa[1].y); u0.w = pk2(pa[1].z, pa[1].w);
            u1.x = pk2(pa[2].x, pa[2].y); u1.y = pk2(pa[2].z, pa[2].w);
            u1.z = pk2(pa[3].x, pa[3].y); u1.w = pk2(pa[3].z, pa[3].w);
            *(uint4*)(as + arow * AP_H + acolb) = u0;
            *(uint4*)(as + arow * AP_H + acolb + 8) = u1;
        }
        uint4 v0, v1;
        v0.x = pk2(pb[0].x, pb[0].y); v0.y = pk2(pb[0].z, pb[0].w);
        v0.z = pk2(pb[1].x, pb[1].y); v0.w = pk2(pb[1].z, pb[1].w);
        v1.x = pk2(pb[2].x, pb[2].y); v1.y = pk2(pb[2].z, pb[2].w);
        v1.z = pk2(pb[3].x, pb[3].y); v1.w = pk2(pb[3].z, pb[3].w);
        *(uint4*)(bs + brow * BP_H + bcolb) = v0;
        *(uint4*)(bs + brow * BP_H + bcolb + 8) = v1;
    };

    float acc[2][8][4];
#pragma unroll
    for (int mt = 0; mt < 2; mt++)
#pragma unroll
        for (int nt = 0; nt < 8; nt++)
#pragma unroll
            for (int c = 0; c < 4; c++) acc[mt][nt][c] = 0.f;

    load_tiles(0);
    store_tiles(0);
    __syncthreads();

    const uint32_t asU = smem_u32(As);
    const uint32_t bsU = smem_u32(Bs);

    for (int it = 0; it < 16; it++) {
        const int cur = it & 1;
        if (it < 15) load_tiles((it + 1) * 32);

        const uint32_t aB = asU + cur * (AS_SZ * 2);
        const uint32_t bB = bsU + cur * (BS_SZ * 2);
#pragma unroll
        for (int ks = 0; ks < 2; ks++) {
            uint32_t a[2][4];
#pragma unroll
            for (int mt = 0; mt < 2; mt++) {
                uint32_t ad = aB + ((wm + mt * 16 + (lane & 15)) * AP_H + ks * 16 + (lane >> 4) * 8) * 2;
                ldm_x4(a[mt][0], a[mt][1], a[mt][2], a[mt][3], ad);
            }
#pragma unroll
            for (int ntp = 0; ntp < 4; ntp++) {
                uint32_t r0, r1, r2, r3;
                uint32_t bd = bB + ((ks * 16 + (lane & 7) + ((lane >> 3) & 1) * 8) * BP_H
                                    + wn + ntp * 16 + ((lane >> 4) << 3)) * 2;
                ldm_x4_t(r0, r1, r2, r3, bd);
                mma_f16(acc[0][2 * ntp], a[0], r0, r1);
                mma_f16(acc[0][2 * ntp + 1], a[0], r2, r3);
                mma_f16(acc[1][2 * ntp], a[1], r0, r1);
                mma_f16(acc[1][2 * ntp + 1], a[1], r2, r3);
            }
        }

        if (it < 15) { store_tiles(cur ^ 1); __syncthreads(); }
    }

    // epilogue
#pragma unroll
    for (int mt = 0; mt < 2; mt++) {
        const int r = row0 + wm + mt * 16 + g;
#pragma unroll
        for (int nt = 0; nt < 8; nt++) {
            const int c = col0 + wn + nt * 8 + 2 * t;
            const float2 bv = *(const float2*)(bias + c);
            if (OUT_HALF) {
                __half* C = (__half*)Cv;
                *(__half2*)(C + (size_t)r * N + c) =
                    __floats2half2_rn((acc[mt][nt][0] + bv.x) * scale, (acc[mt][nt][1] + bv.y) * scale);
                *(__half2*)(C + (size_t)(r + 8) * N + c) =
                    __floats2half2_rn((acc[mt][nt][2] + bv.x) * scale, (acc[mt][nt][3] + bv.y) * scale);
            } else {
                float* C = (float*)Cv;
                *(float2*)(C + (size_t)r * N + c) =
                    make_float2(acc[mt][nt][0] + bv.x, acc[mt][nt][1] + bv.y);
                *(float2*)(C + (size_t)(r + 8) * N + c) =
                    make_float2(acc[mt][nt][2] + bv.x, acc[mt][nt][3] + bv.y);
            }
        }
    }
}

#define G_SMEM_HALVES (2 * AS_SZ + 2 * BS_SZ)   // 18944 halves = 37888 B

__global__ __launch_bounds__(256) void proj_dual(
    const float* __restrict__ query, const float* __restrict__ value,
    const float* __restrict__ wq, const float* __restrict__ wqb,
    const float* __restrict__ wkv, const float* __restrict__ wkvb,
    __half* __restrict__ outq, __half* __restrict__ outkv)
{
    __shared__ __half smh[G_SMEM_HALVES];
    const int bx = blockIdx.x, by = blockIdx.y;
    const float QSCALE = 0.125f * 1.44269504089f;   // fold softmax scale + log2(e)
    if (bx < 4)
        gemm_tc<false, true>(query, wq, wqb, outq, D_MODEL, by * 128, bx * 128, QSCALE, smh);
    else
        gemm_tc<false, true>(value, wkv, wkvb, outkv, KV_W, by * 128, (bx - 4) * 128, 1.0f, smh);
}

__global__ __launch_bounds__(256) void out_proj(
    const __half* __restrict__ A, const float* __restrict__ B,
    const float* __restrict__ bias, float* __restrict__ C)
{
    __shared__ __half smh[G_SMEM_HALVES];
    gemm_tc<true, false>(A, B, bias, C, D_MODEL, blockIdx.y * 128, blockIdx.x * 128, 1.0f, smh);
}

// ---------------- causal flash attention, fp16 mma + cp.async ----------------
// 128 threads = 4 warps; CTA tile 128q x 64k; warp tile 32q x 64k.
// Softmax in exp2 domain (Q pre-scaled by 0.125*log2e at projection).
#define QP 72            // pitches in halves (144B rows)
#define QS_SZ (128 * QP)
#define KT_SZ (64 * QP)
#define FA_SMEM_BYTES ((QS_SZ + 4 * KT_SZ) * 2)   // 55296

__global__ __launch_bounds__(128) void flash_attn_h(
    const __half* __restrict__ Qh, const __half* __restrict__ KVh,
    __half* __restrict__ Oh)
{
    extern __shared__ __half smh[];
    __half* Qs = smh;
    __half* KsB = smh + QS_SZ;             // [2][64][72]
    __half* VsB = smh + QS_SZ + 2 * KT_SZ; // [2][64][72]

    const int qb = gridDim.x - 1 - blockIdx.x;   // heavy first
    const int h  = blockIdx.y;
    const int tid = threadIdx.x;
    const int lane = tid & 31, warp = tid >> 5;
    const int g = lane >> 2, t = lane & 3;
    const int wq = warp * 32;
    const int q0 = qb * 128;
    const int ntiles = 2 * qb + 2;

    const uint32_t qsU = smem_u32(Qs);
    const uint32_t ksU = smem_u32(KsB);
    const uint32_t vsU = smem_u32(VsB);

    // stage Q (1024 16B chunks)
#pragma unroll
    for (int i = 0; i < 8; i++) {
        const int c = tid + 128 * i;
        const int row = c >> 3, seg = (c & 7) * 8;
        cp_async16(qsU + (row * QP + seg) * 2,
                   Qh + (size_t)(q0 + row) * D_MODEL + h * 64 + seg);
    }
    auto stage_kv = [&](int kb, int buf) {
        const int k0 = kb * 64;
        const uint32_t kd = ksU + buf * KT_SZ * 2;
        const uint32_t vd = vsU + buf * KT_SZ * 2;
#pragma unroll
        for (int i = 0; i < 4; i++) {
            const int c = tid + 128 * i;
            const int row = c >> 3, seg = (c & 7) * 8;
            const size_t base = (size_t)(k0 + row) * KV_W + h * 64 + seg;
            cp_async16(kd + (row * QP + seg) * 2, KVh + base);
            cp_async16(vd + (row * QP + seg) * 2, KVh + base + D_MODEL);
        }
    };
    stage_kv(0, 0);
    cp_commit();

    float o[2][8][4];
    float m_i[4], l_i[4];
#pragma unroll
    for (int i = 0; i < 4; i++) { m_i[i] = -1e30f; l_i[i] = 0.f; }
#pragma unroll
    for (int mt = 0; mt < 2; mt++)
#pragma unroll
        for (int nt = 0; nt < 8; nt++)
#pragma unroll
            for (int c = 0; c < 4; c++) o[mt][nt][c] = 0.f;

    for (int kb = 0; kb < ntiles; kb++) {
        const int buf = kb & 1;
        const int k0 = kb * 64;

        __syncthreads();   // prior compute done before prefetch overwrites buf^1
        if (kb + 1 < ntiles) { stage_kv(kb + 1, buf ^ 1); cp_commit(); cp_wait<1>(); }
        else cp_wait<0>();
        __syncthreads();

        const uint32_t kB = ksU + buf * KT_SZ * 2;
        const uint32_t vB = vsU + buf * KT_SZ * 2;

        // ---- S = Q K^T ----
        float s[2][8][4];
#pragma unroll
        for (int mt = 0; mt < 2; mt++)
#pragma unroll
            for (int nt = 0; nt < 8; nt++)
#pragma unroll
                for (int c = 0; c < 4; c++) s[mt][nt][c] = 0.f;

#pragma unroll
        for (int ks = 0; ks < 4; ks++) {
            uint32_t a[2][4];
#pragma unroll
            for (int mt = 0; mt < 2; mt++) {
                uint32_t ad = qsU + ((wq + mt * 16 + (lane & 15)) * QP + ks * 16 + (lane >> 4) * 8) * 2;
                ldm_x4(a[mt][0], a[mt][1], a[mt][2], a[mt][3], ad);
            }
#pragma unroll
            for (int ntp = 0; ntp < 4; ntp++) {
                uint32_t r0, r1, r2, r3;
                uint32_t bd = kB + ((ntp * 16 + (lane & 7) + ((lane >> 4) << 3)) * QP
                                    + ks * 16 + ((lane >> 3) & 1) * 8) * 2;
                ldm_x4(r0, r1, r2, r3, bd);   // non-trans: Ks is [key][hd] = [n][k]
                mma_f16(s[0][2 * ntp], a[0], r0, r1);
                mma_f16(s[0][2 * ntp + 1], a[0], r2, r3);
                mma_f16(s[1][2 * ntp], a[1], r0, r1);
                mma_f16(s[1][2 * ntp + 1], a[1], r2, r3);
            }
        }

        // causal mask (diagonal-region tiles only)
        if (kb >= 2 * qb) {
#pragma unroll
            for (int mt = 0; mt < 2; mt++)
#pragma unroll
                for (int nt = 0; nt < 8; nt++)
#pragma unroll
                    for (int c = 0; c < 4; c++) {
                        const int row = q0 + wq + mt * 16 + g + (c >> 1) * 8;
                        const int col = k0 + nt * 8 + 2 * t + (c & 1);
                        if (col > row) s[mt][nt][c] = -1e30f;
                    }
        }

        // ---- online softmax (exp2 domain) ----
#pragma unroll
        for (int mt = 0; mt < 2; mt++) {
#pragma unroll
            for (int sr = 0; sr < 2; sr++) {
                const int idx = mt * 2 + sr;
                float mx = -1e30f;
#pragma unroll
                for (int nt = 0; nt < 8; nt++)
                    mx = fmaxf(mx, fmaxf(s[mt][nt][2 * sr], s[mt][nt][2 * sr + 1]));
                mx = fmaxf(mx, __shfl_xor_sync(0xffffffffu, mx, 1, 4));
                mx = fmaxf(mx, __shfl_xor_sync(0xffffffffu, mx, 2, 4));

                const float m_new = fmaxf(m_i[idx], mx);
                const float alpha = fexp2(m_i[idx] - m_new);
                float rs = 0.f;
#pragma unroll
                for (int nt = 0; nt < 8; nt++) {
                    const float p0 = fexp2(s[mt][nt][2 * sr] - m_new);
                    const float p1 = fexp2(s[mt][nt][2 * sr + 1] - m_new);
                    s[mt][nt][2 * sr] = p0;
                    s[mt][nt][2 * sr + 1] = p1;
                    rs += p0 + p1;
                }
                rs += __shfl_xor_sync(0xffffffffu, rs, 1, 4);
                rs += __shfl_xor_sync(0xffffffffu, rs, 2, 4);

                l_i[idx] = l_i[idx] * alpha + rs;
                m_i[idx] = m_new;
#pragma unroll
                for (int nt = 0; nt < 8; nt++) {
                    o[mt][nt][2 * sr] *= alpha;
                    o[mt][nt][2 * sr + 1] *= alpha;
                }
            }
        }

        // ---- O += P V (P straight from registers) ----
#pragma unroll
        for (int ksp = 0; ksp < 4; ksp++) {
            uint32_t aP[2][4];
#pragma unroll
            for (int mt = 0; mt < 2; mt++) {
                aP[mt][0] = pk2(s[mt][2 * ksp][0], s[mt][2 * ksp][1]);
                aP[mt][1] = pk2(s[mt][2 * ksp][2], s[mt][2 * ksp][3]);
                aP[mt][2] = pk2(s[mt][2 * ksp + 1][0], s[mt][2 * ksp + 1][1]);
                aP[mt][3] = pk2(s[mt][2 * ksp + 1][2], s[mt][2 * ksp + 1][3]);
            }
#pragma unroll
            for (int ntp = 0; ntp < 4; ntp++) {
                uint32_t r0, r1, r2, r3;
                uint32_t bd = vB + ((ksp * 16 + (lane & 7) + ((lane >> 3) & 1) * 8) * QP
                                    + ntp * 16 + ((lane >> 4) << 3)) * 2;
                ldm_x4_t(r0, r1, r2, r3, bd);   // trans: Vs is [key][hd] = [k][n]
                mma_f16(o[0][2 * ntp], aP[0], r0, r1);
                mma_f16(o[0][2 * ntp + 1], aP[0], r2, r3);
                mma_f16(o[1][2 * ntp], aP[1], r0, r1);
                mma_f16(o[1][2 * ntp + 1], aP[1], r2, r3);
            }
        }
    }

    // normalize + store (half)
#pragma unroll
    for (int mt = 0; mt < 2; mt++) {
#pragma unroll
        for (int sr = 0; sr < 2; sr++) {
            const float inv = 1.f / l_i[mt * 2 + sr];
            const int r = q0 + wq + mt * 16 + g + 8 * sr;
#pragma unroll
            for (int nt = 0; nt < 8; nt++) {
                *(__half2*)(Oh + (size_t)r * D_MODEL + h * 64 + nt * 8 + 2 * t) =
                    __floats2half2_rn(o[mt][nt][2 * sr] * inv, o[mt][nt][2 * sr + 1] * inv);
            }
        }
    }
}

// ---------------- launch ----------------
extern "C" void kernel_launch(void* const* d_in, const int* in_sizes, int n_in,
                              void* d_out, int out_size)
{
    const float* query = (const float*)d_in[0];
    const float* value = (const float*)d_in[1];
    // d_in[2]: additive causal mask -> handled structurally
    const float* wq_k  = (const float*)d_in[3];
    const float* wq_b  = (const float*)d_in[4];
    const float* wkv_k = (const float*)d_in[5];
    const float* wkv_b = (const float*)d_in[6];
    const float* wo_k  = (const float*)d_in[7];
    const float* wo_b  = (const float*)d_in[8];
    float* out = (float*)d_out;

    __half *q_ptr = nullptr, *kv_ptr = nullptr, *att_ptr = nullptr;
    cudaGetSymbolAddress((void**)&q_ptr,  g_q);
    cudaGetSymbolAddress((void**)&kv_ptr, g_kv);
    cudaGetSymbolAddress((void**)&att_ptr, g_att);

    proj_dual<<<dim3(12, 32), 256>>>(query, value, wq_k, wq_b, wkv_k, wkv_b,
                                     q_ptr, kv_ptr);

    cudaFuncSetAttribute(flash_attn_h, cudaFuncAttributeMaxDynamicSharedMemorySize, FA_SMEM_BYTES);
    flash_attn_h<<<dim3(S_LEN / 128, N_HEADS), 128, FA_SMEM_BYTES>>>(q_ptr, kv_ptr, att_ptr);

    out_proj<<<dim3(4, 32), 256>>>(att_ptr, wo_k, wo_b, out);
}

// round 12
// speedup vs baseline: 1.0039x; 1.0003x over previous
#include <cuda_runtime.h>
#include <cuda_fp16.h>
#include <cstdint>

#define S_LEN 4096
#define D_MODEL 512
#define KV_W 1024
#define N_HEADS 8

// ---------------- scratch (fp16 intermediates) ----------------
__device__ __half g_q[S_LEN * D_MODEL];    // pre-scaled by 0.125*log2(e)
__device__ __half g_kv[S_LEN * KV_W];
__device__ __half g_att[S_LEN * D_MODEL];

// ---------------- helpers ----------------
__device__ __forceinline__ uint32_t smem_u32(const void* p) {
    return (uint32_t)__cvta_generic_to_shared(p);
}
__device__ __forceinline__ uint32_t pk2(float lo, float hi) {
    __half2 h = __floats2half2_rn(lo, hi);
    return *reinterpret_cast<uint32_t*>(&h);
}
__device__ __forceinline__ float fexp2(float x) {
    float y; asm("ex2.approx.f32 %0, %1;" : "=f"(y) : "f"(x)); return y;
}
__device__ __forceinline__ void ldm_x4(uint32_t& r0, uint32_t& r1, uint32_t& r2, uint32_t& r3, uint32_t a) {
    asm volatile("ldmatrix.sync.aligned.m8n8.x4.shared.b16 {%0,%1,%2,%3}, [%4];"
                 : "=r"(r0), "=r"(r1), "=r"(r2), "=r"(r3) : "r"(a));
}
__device__ __forceinline__ void ldm_x4_t(uint32_t& r0, uint32_t& r1, uint32_t& r2, uint32_t& r3, uint32_t a) {
    asm volatile("ldmatrix.sync.aligned.m8n8.x4.trans.shared.b16 {%0,%1,%2,%3}, [%4];"
                 : "=r"(r0), "=r"(r1), "=r"(r2), "=r"(r3) : "r"(a));
}
// D += A(16x16) * B(16x8), f16 in, f32 accum
__device__ __forceinline__ void mma_f16(float* d, const uint32_t* a, uint32_t b0, uint32_t b1) {
    asm volatile(
        "mma.sync.aligned.m16n8k16.row.col.f32.f16.f16.f32 "
        "{%0,%1,%2,%3}, {%4,%5,%6,%7}, {%8,%9}, {%0,%1,%2,%3};"
        : "+f"(d[0]), "+f"(d[1]), "+f"(d[2]), "+f"(d[3])
        : "r"(a[0]), "r"(a[1]), "r"(a[2]), "r"(a[3]), "r"(b0), "r"(b1));
}
__device__ __forceinline__ void cp_async16(uint32_t dst, const void* src) {
    asm volatile("cp.async.cg.shared.global [%0], [%1], 16;" :: "r"(dst), "l"(src));
}
__device__ __forceinline__ void cp_commit() { asm volatile("cp.async.commit_group;" ::: "memory"); }
template<int N> __device__ __forceinline__ void cp_wait() {
    asm volatile("cp.async.wait_group %0;" :: "n"(N) : "memory");
}

// ---------------- fp16 tensor-core GEMM ----------------
// C[M,N] = A[M,512] @ B[512,N] + bias, BM=128 BN=128 BK=32, 256 thr (8 warps 4m x 2n).
#define AP_H 40     // As pitch, halves (80B rows: 20r mod 32 distinct bank groups)
#define BP_H 136    // Bs pitch, halves (272B rows: 4r mod 32)
#define AS_SZ (128 * AP_H)   // 5120 halves
#define BS_SZ (32 * BP_H)    // 4352 halves

template<bool A_HALF, bool OUT_HALF>
__device__ __forceinline__ void gemm_tc(
    const void* Av, const float* __restrict__ B, const float* __restrict__ bias,
    void* Cv, int N, int row0, int col0, float scale, __half* smh)
{
    __half* As = smh;                    // [2][128][40]
    __half* Bs = smh + 2 * AS_SZ;        // [2][32][136]

    const int tid = threadIdx.x;
    const int lane = tid & 31, warp = tid >> 5;
    const int wm = (warp & 3) * 32, wn = (warp >> 2) * 64;
    const int g = lane >> 2, t = lane & 3;

    const float* Af = (const float*)Av;
    const __half* Ah = (const __half*)Av;

    const int arow = tid >> 1, acolb = (tid & 1) * 16;
    const int brow = tid >> 3, bcolb = (tid & 7) * 16;

    float4 pa[4]; uint4 pah[2]; float4 pb[4];

    auto load_tiles = [&](int k0) {
        if (A_HALF) {
            const __half* p = Ah + (size_t)(row0 + arow) * 512 + k0 + acolb;
            pah[0] = *(const uint4*)(p);
            pah[1] = *(const uint4*)(p + 8);
        } else {
            const float* p = Af + (size_t)(row0 + arow) * 512 + k0 + acolb;
#pragma unroll
            for (int j = 0; j < 4; j++) pa[j] = *(const float4*)(p + j * 4);
        }
        const float* q = B + (size_t)(k0 + brow) * N + col0 + bcolb;
#pragma unroll
        for (int j = 0; j < 4; j++) pb[j] = *(const float4*)(q + j * 4);
    };
    auto store_tiles = [&](int buf) {
        __half* as = As + buf * AS_SZ;
        __half* bs = Bs + buf * BS_SZ;
        if (A_HALF) {
            *(uint4*)(as + arow * AP_H + acolb) = pah[0];
            *(uint4*)(as + arow * AP_H + acolb + 8) = pah[1];
        } else {
            uint4 u0, u1;
            u0.x = pk2(pa[0].x, pa[0].y); u0.y = pk2(pa[0].z, pa[0].w);
            u0.z = pk2(pa[1].x, pa[1].y); u0.w = pk2(pa[1].z, pa[1].w);
            u1.x = pk2(pa[2].x, pa[2].y); u1.y = pk2(pa[2].z, pa[2].w);
            u1.z = pk2(pa[3].x, pa[3].y); u1.w = pk2(pa[3].z, pa[3].w);
            *(uint4*)(as + arow * AP_H + acolb) = u0;
            *(uint4*)(as + arow * AP_H + acolb + 8) = u1;
        }
        uint4 v0, v1;
        v0.x = pk2(pb[0].x, pb[0].y); v0.y = pk2(pb[0].z, pb[0].w);
        v0.z = pk2(pb[1].x, pb[1].y); v0.w = pk2(pb[1].z, pb[1].w);
        v1.x = pk2(pb[2].x, pb[2].y); v1.y = pk2(pb[2].z, pb[2].w);
        v1.z = pk2(pb[3].x, pb[3].y); v1.w = pk2(pb[3].z, pb[3].w);
        *(uint4*)(bs + brow * BP_H + bcolb) = v0;
        *(uint4*)(bs + brow * BP_H + bcolb + 8) = v1;
    };

    float acc[2][8][4];
#pragma unroll
    for (int mt = 0; mt < 2; mt++)
#pragma unroll
        for (int nt = 0; nt < 8; nt++)
#pragma unroll
            for (int c = 0; c < 4; c++) acc[mt][nt][c] = 0.f;

    load_tiles(0);
    store_tiles(0);
    __syncthreads();

    const uint32_t asU = smem_u32(As);
    const uint32_t bsU = smem_u32(Bs);

    for (int it = 0; it < 16; it++) {
        const int cur = it & 1;
        if (it < 15) load_tiles((it + 1) * 32);

        const uint32_t aB = asU + cur * (AS_SZ * 2);
        const uint32_t bB = bsU + cur * (BS_SZ * 2);
#pragma unroll
        for (int ks = 0; ks < 2; ks++) {
            uint32_t a[2][4];
#pragma unroll
            for (int mt = 0; mt < 2; mt++) {
                uint32_t ad = aB + ((wm + mt * 16 + (lane & 15)) * AP_H + ks * 16 + (lane >> 4) * 8) * 2;
                ldm_x4(a[mt][0], a[mt][1], a[mt][2], a[mt][3], ad);
            }
#pragma unroll
            for (int ntp = 0; ntp < 4; ntp++) {
                uint32_t r0, r1, r2, r3;
                uint32_t bd = bB + ((ks * 16 + (lane & 7) + ((lane >> 3) & 1) * 8) * BP_H
                                    + wn + ntp * 16 + ((lane >> 4) << 3)) * 2;
                ldm_x4_t(r0, r1, r2, r3, bd);
                mma_f16(acc[0][2 * ntp], a[0], r0, r1);
                mma_f16(acc[0][2 * ntp + 1], a[0], r2, r3);
                mma_f16(acc[1][2 * ntp], a[1], r0, r1);
                mma_f16(acc[1][2 * ntp + 1], a[1], r2, r3);
            }
        }

        if (it < 15) { store_tiles(cur ^ 1); __syncthreads(); }
    }

    // epilogue
#pragma unroll
    for (int mt = 0; mt < 2; mt++) {
        const int r = row0 + wm + mt * 16 + g;
#pragma unroll
        for (int nt = 0; nt < 8; nt++) {
            const int c = col0 + wn + nt * 8 + 2 * t;
            const float2 bv = *(const float2*)(bias + c);
            if (OUT_HALF) {
                __half* C = (__half*)Cv;
                *(__half2*)(C + (size_t)r * N + c) =
                    __floats2half2_rn((acc[mt][nt][0] + bv.x) * scale, (acc[mt][nt][1] + bv.y) * scale);
                *(__half2*)(C + (size_t)(r + 8) * N + c) =
                    __floats2half2_rn((acc[mt][nt][2] + bv.x) * scale, (acc[mt][nt][3] + bv.y) * scale);
            } else {
                float* C = (float*)Cv;
                *(float2*)(C + (size_t)r * N + c) =
                    make_float2(acc[mt][nt][0] + bv.x, acc[mt][nt][1] + bv.y);
                *(float2*)(C + (size_t)(r + 8) * N + c) =
                    make_float2(acc[mt][nt][2] + bv.x, acc[mt][nt][3] + bv.y);
            }
        }
    }
}

#define G_SMEM_HALVES (2 * AS_SZ + 2 * BS_SZ)   // 18944 halves = 37888 B

__global__ __launch_bounds__(256) void proj_dual(
    const float* __restrict__ query, const float* __restrict__ value,
    const float* __restrict__ wq, const float* __restrict__ wqb,
    const float* __restrict__ wkv, const float* __restrict__ wkvb,
    __half* __restrict__ outq, __half* __restrict__ outkv)
{
    __shared__ __half smh[G_SMEM_HALVES];
    const int bx = blockIdx.x, by = blockIdx.y;
    const float QSCALE = 0.125f * 1.44269504089f;   // fold softmax scale + log2(e)
    if (bx < 4)
        gemm_tc<false, true>(query, wq, wqb, outq, D_MODEL, by * 128, bx * 128, QSCALE, smh);
    else
        gemm_tc<false, true>(value, wkv, wkvb, outkv, KV_W, by * 128, (bx - 4) * 128, 1.0f, smh);
}

__global__ __launch_bounds__(256) void out_proj(
    const __half* __restrict__ A, const float* __restrict__ B,
    const float* __restrict__ bias, float* __restrict__ C)
{
    __shared__ __half smh[G_SMEM_HALVES];
    gemm_tc<true, false>(A, B, bias, C, D_MODEL, blockIdx.y * 128, blockIdx.x * 128, 1.0f, smh);
}

// ---------------- causal flash attention, fp16 mma + cp.async ----------------
// 128 threads = 4 warps; CTA tile 128q x 64k; warp tile 32q x 64k.
// Softmax in exp2 domain (Q pre-scaled by 0.125*log2e at projection).
#define QP 72            // pitches in halves (144B rows)
#define QS_SZ (128 * QP)
#define KT_SZ (64 * QP)
#define FA_SMEM_BYTES ((QS_SZ + 4 * KT_SZ) * 2)   // 55296

__global__ __launch_bounds__(128) void flash_attn_h(
    const __half* __restrict__ Qh, const __half* __restrict__ KVh,
    __half* __restrict__ Oh)
{
    extern __shared__ __half smh[];
    __half* Qs = smh;
    __half* KsB = smh + QS_SZ;             // [2][64][72]
    __half* VsB = smh + QS_SZ + 2 * KT_SZ; // [2][64][72]

    const int qb = gridDim.x - 1 - blockIdx.x;   // heavy first
    const int h  = blockIdx.y;
    const int tid = threadIdx.x;
    const int lane = tid & 31, warp = tid >> 5;
    const int g = lane >> 2, t = lane & 3;
    const int wq = warp * 32;
    const int q0 = qb * 128;
    const int ntiles = 2 * qb + 2;

    const uint32_t qsU = smem_u32(Qs);
    const uint32_t ksU = smem_u32(KsB);
    const uint32_t vsU = smem_u32(VsB);

    // stage Q (1024 16B chunks)
#pragma unroll
    for (int i = 0; i < 8; i++) {
        const int c = tid + 128 * i;
        const int row = c >> 3, seg = (c & 7) * 8;
        cp_async16(qsU + (row * QP + seg) * 2,
                   Qh + (size_t)(q0 + row) * D_MODEL + h * 64 + seg);
    }
    auto stage_kv = [&](int kb, int buf) {
        const int k0 = kb * 64;
        const uint32_t kd = ksU + buf * KT_SZ * 2;
        const uint32_t vd = vsU + buf * KT_SZ * 2;
#pragma unroll
        for (int i = 0; i < 4; i++) {
            const int c = tid + 128 * i;
            const int row = c >> 3, seg = (c & 7) * 8;
            const size_t base = (size_t)(k0 + row) * KV_W + h * 64 + seg;
            cp_async16(kd + (row * QP + seg) * 2, KVh + base);
            cp_async16(vd + (row * QP + seg) * 2, KVh + base + D_MODEL);
        }
    };
    stage_kv(0, 0);
    cp_commit();

    float o[2][8][4];
    float m_i[4], l_i[4];
#pragma unroll
    for (int i = 0; i < 4; i++) { m_i[i] = -1e30f; l_i[i] = 0.f; }
#pragma unroll
    for (int mt = 0; mt < 2; mt++)
#pragma unroll
        for (int nt = 0; nt < 8; nt++)
#pragma unroll
            for (int c = 0; c < 4; c++) o[mt][nt][c] = 0.f;

    for (int kb = 0; kb < ntiles; kb++) {
        const int buf = kb & 1;
        const int k0 = kb * 64;

        __syncthreads();   // prior compute done before prefetch overwrites buf^1
        if (kb + 1 < ntiles) { stage_kv(kb + 1, buf ^ 1); cp_commit(); cp_wait<1>(); }
        else cp_wait<0>();
        __syncthreads();

        const uint32_t kB = ksU + buf * KT_SZ * 2;
        const uint32_t vB = vsU + buf * KT_SZ * 2;

        // ---- S = Q K^T ----
        float s[2][8][4];
#pragma unroll
        for (int mt = 0; mt < 2; mt++)
#pragma unroll
            for (int nt = 0; nt < 8; nt++)
#pragma unroll
                for (int c = 0; c < 4; c++) s[mt][nt][c] = 0.f;

#pragma unroll
        for (int ks = 0; ks < 4; ks++) {
            uint32_t a[2][4];
#pragma unroll
            for (int mt = 0; mt < 2; mt++) {
                uint32_t ad = qsU + ((wq + mt * 16 + (lane & 15)) * QP + ks * 16 + (lane >> 4) * 8) * 2;
                ldm_x4(a[mt][0], a[mt][1], a[mt][2], a[mt][3], ad);
            }
#pragma unroll
            for (int ntp = 0; ntp < 4; ntp++) {
                uint32_t r0, r1, r2, r3;
                uint32_t bd = kB + ((ntp * 16 + (lane & 7) + ((lane >> 4) << 3)) * QP
                                    + ks * 16 + ((lane >> 3) & 1) * 8) * 2;
                ldm_x4(r0, r1, r2, r3, bd);   // non-trans: Ks is [key][hd] = [n][k]
                mma_f16(s[0][2 * ntp], a[0], r0, r1);
                mma_f16(s[0][2 * ntp + 1], a[0], r2, r3);
                mma_f16(s[1][2 * ntp], a[1], r0, r1);
                mma_f16(s[1][2 * ntp + 1], a[1], r2, r3);
            }
        }

        // causal mask (diagonal-region tiles only)
        if (kb >= 2 * qb) {
#pragma unroll
            for (int mt = 0; mt < 2; mt++)
#pragma unroll
                for (int nt = 0; nt < 8; nt++)
#pragma unroll
                    for (int c = 0; c < 4; c++) {
                        const int row = q0 + wq + mt * 16 + g + (c >> 1) * 8;
                        const int col = k0 + nt * 8 + 2 * t + (c & 1);
                        if (col > row) s[mt][nt][c] = -1e30f;
                    }
        }

        // ---- online softmax (exp2 domain) ----
#pragma unroll
        for (int mt = 0; mt < 2; mt++) {
#pragma unroll
            for (int sr = 0; sr < 2; sr++) {
                const int idx = mt * 2 + sr;
                float mx = -1e30f;
#pragma unroll
                for (int nt = 0; nt < 8; nt++)
                    mx = fmaxf(mx, fmaxf(s[mt][nt][2 * sr], s[mt][nt][2 * sr + 1]));
                mx = fmaxf(mx, __shfl_xor_sync(0xffffffffu, mx, 1, 4));
                mx = fmaxf(mx, __shfl_xor_sync(0xffffffffu, mx, 2, 4));

                const float m_new = fmaxf(m_i[idx], mx);
                const float alpha = fexp2(m_i[idx] - m_new);
                float rs = 0.f;
#pragma unroll
                for (int nt = 0; nt < 8; nt++) {
                    const float p0 = fexp2(s[mt][nt][2 * sr] - m_new);
                    const float p1 = fexp2(s[mt][nt][2 * sr + 1] - m_new);
                    s[mt][nt][2 * sr] = p0;
                    s[mt][nt][2 * sr + 1] = p1;
                    rs += p0 + p1;
                }
                rs += __shfl_xor_sync(0xffffffffu, rs, 1, 4);
                rs += __shfl_xor_sync(0xffffffffu, rs, 2, 4);

                l_i[idx] = l_i[idx] * alpha + rs;
                m_i[idx] = m_new;
#pragma unroll
                for (int nt = 0; nt < 8; nt++) {
                    o[mt][nt][2 * sr] *= alpha;
                    o[mt][nt][2 * sr + 1] *= alpha;
                }
            }
        }

        // ---- O += P V (P straight from registers) ----
#pragma unroll
        for (int ksp = 0; ksp < 4; ksp++) {
            uint32_t aP[2][4];
#pragma unroll
            for (int mt = 0; mt < 2; mt++) {
                aP[mt][0] = pk2(s[mt][2 * ksp][0], s[mt][2 * ksp][1]);
                aP[mt][1] = pk2(s[mt][2 * ksp][2], s[mt][2 * ksp][3]);
                aP[mt][2] = pk2(s[mt][2 * ksp + 1][0], s[mt][2 * ksp + 1][1]);
                aP[mt][3] = pk2(s[mt][2 * ksp + 1][2], s[mt][2 * ksp + 1][3]);
            }
#pragma unroll
            for (int ntp = 0; ntp < 4; ntp++) {
                uint32_t r0, r1, r2, r3;
                uint32_t bd = vB + ((ksp * 16 + (lane & 7) + ((lane >> 3) & 1) * 8) * QP
                                    + ntp * 16 + ((lane >> 4) << 3)) * 2;
                ldm_x4_t(r0, r1, r2, r3, bd);   // trans: Vs is [key][hd] = [k][n]
                mma_f16(o[0][2 * ntp], aP[0], r0, r1);
                mma_f16(o[0][2 * ntp + 1], aP[0], r2, r3);
                mma_f16(o[1][2 * ntp], aP[1], r0, r1);
                mma_f16(o[1][2 * ntp + 1], aP[1], r2, r3);
            }
        }
    }

    // normalize + store (half)
#pragma unroll
    for (int mt = 0; mt < 2; mt++) {
#pragma unroll
        for (int sr = 0; sr < 2; sr++) {
            const float inv = 1.f / l_i[mt * 2 + sr];
            const int r = q0 + wq + mt * 16 + g + 8 * sr;
#pragma unroll
            for (int nt = 0; nt < 8; nt++) {
                *(__half2*)(Oh + (size_t)r * D_MODEL + h * 64 + nt * 8 + 2 * t) =
                    __floats2half2_rn(o[mt][nt][2 * sr] * inv, o[mt][nt][2 * sr + 1] * inv);
            }
        }
    }
}

// ---------------- launch ----------------
extern "C" void kernel_launch(void* const* d_in, const int* in_sizes, int n_in,
                              void* d_out, int out_size)
{
    const float* query = (const float*)d_in[0];
    const float* value = (const float*)d_in[1];
    // d_in[2]: additive causal mask -> handled structurally
    const float* wq_k  = (const float*)d_in[3];
    const float* wq_b  = (const float*)d_in[4];
    const float* wkv_k = (const float*)d_in[5];
    const float* wkv_b = (const float*)d_in[6];
    const float* wo_k  = (const float*)d_in[7];
    const float* wo_b  = (const float*)d_in[8];
    float* out = (float*)d_out;

    __half *q_ptr = nullptr, *kv_ptr = nullptr, *att_ptr = nullptr;
    cudaGetSymbolAddress((void**)&q_ptr,  g_q);
    cudaGetSymbolAddress((void**)&kv_ptr, g_kv);
    cudaGetSymbolAddress((void**)&att_ptr, g_att);

    proj_dual<<<dim3(12, 32), 256>>>(query, value, wq_k, wq_b, wkv_k, wkv_b,
                                     q_ptr, kv_ptr);

    cudaFuncSetAttribute(flash_attn_h, cudaFuncAttributeMaxDynamicSharedMemorySize, FA_SMEM_BYTES);
    flash_attn_h<<<dim3(S_LEN / 128, N_HEADS), 128, FA_SMEM_BYTES>>>(q_ptr, kv_ptr, att_ptr);

    out_proj<<<dim3(4, 32), 256>>>(att_ptr, wo_k, wo_b, out);
}